// round 3
// baseline (speedup 1.0000x reference)
#include <cuda_runtime.h>

#define H_  8
#define B_  4
#define C_  256
#define N_  2048
#define HD_ 64
#define O_  512
#define HB_ 32   // H_*B_

// ---------------- scratch (device globals; no allocations allowed) ----------------
__device__ float g_qT[HB_ * HD_ * N_];         // [hb][d][n]   (transposed for pass1)
__device__ float g_kT[HB_ * HD_ * N_];         // [hb][d][n]
__device__ float g_v [HB_ * N_ * HD_];         // [hb][n][d]
__device__ float g_yp[B_ * N_ * HD_];          // [b][n][d]
__device__ float g_E [(size_t)HB_ * N_ * N_];  // [hb][n][m]  raw logits, fp32 (536 MB)
__device__ float g_rmax[HB_ * N_];             // row max over m
__device__ float g_rsum[HB_ * N_];             // row sum of exp(E - rmax)

// ---------------- kernel 1: 1x1 conv projections ----------------
// out tile: 64 (o) x 128 (n) per CTA; K = C = 256 in chunks of 32.
// mode 0: write [hb][n][d] (row-major, for V / yp)
// mode 1: write [hb][d][n] (transposed, for Q / K)
__global__ __launch_bounds__(256) void proj_kernel(
    const float* __restrict__ W, const float* __restrict__ bias,
    const float* __restrict__ in, float* __restrict__ out, int transposed)
{
    __shared__ float Ws[32][68];    // [c'][o]
    __shared__ float Xs[32][132];   // [c'][n]

    int b   = blockIdx.z;
    int o0  = blockIdx.y * 64;
    int n0  = blockIdx.x * 128;
    int tid = threadIdx.x;
    int tx  = tid & 15;   // -> d (4 per thread)
    int ty  = tid >> 4;   // -> n (8 per thread)

    float acc[8][4];
#pragma unroll
    for (int i = 0; i < 8; i++)
#pragma unroll
        for (int j = 0; j < 4; j++) acc[i][j] = 0.f;

    const float* inb = in + (size_t)b * C_ * N_;

    for (int c0 = 0; c0 < C_; c0 += 32) {
        __syncthreads();
        // W tile: Ws[c'][d]  (scalar, coalesced over c)
        {
            int cc = tid & 31;
            int d0 = tid >> 5;            // 0..7
#pragma unroll
            for (int k = 0; k < 8; k++) {
                int d = d0 + 8 * k;       // 0..63
                Ws[cc][d] = W[(size_t)(o0 + d) * C_ + c0 + cc];
            }
        }
        // X tile: Xs[c'][n]  (float4, coalesced over n)
        {
            int n4  = tid & 31;           // n = n4*4
            int c0p = tid >> 5;           // 0..7
#pragma unroll
            for (int k = 0; k < 4; k++) {
                int cp = c0p + 8 * k;     // 0..31
                *(float4*)&Xs[cp][n4 * 4] =
                    *(const float4*)(inb + (size_t)(c0 + cp) * N_ + n0 + n4 * 4);
            }
        }
        __syncthreads();
#pragma unroll 8
        for (int cp = 0; cp < 32; cp++) {
            float4 w4 = *(float4*)&Ws[cp][tx * 4];
            float4 xa = *(float4*)&Xs[cp][ty * 8];
            float4 xb = *(float4*)&Xs[cp][ty * 8 + 4];
            float xx[8] = {xa.x, xa.y, xa.z, xa.w, xb.x, xb.y, xb.z, xb.w};
            float ww[4] = {w4.x, w4.y, w4.z, w4.w};
#pragma unroll
            for (int i = 0; i < 8; i++)
#pragma unroll
                for (int j = 0; j < 4; j++) acc[i][j] += xx[i] * ww[j];
        }
    }

    float bb[4] = {0.f, 0.f, 0.f, 0.f};
    if (bias) {
        float4 b4 = *(const float4*)(bias + o0 + tx * 4);
        bb[0] = b4.x; bb[1] = b4.y; bb[2] = b4.z; bb[3] = b4.w;
    }

    int hb = blockIdx.y * B_ + b;   // for yp (gridDim.y==1) this is just b
    if (!transposed) {
        float* og = out + (size_t)hb * N_ * HD_;
#pragma unroll
        for (int i = 0; i < 8; i++) {
            int n = n0 + ty * 8 + i;
            float4 v;
            v.x = acc[i][0] + bb[0]; v.y = acc[i][1] + bb[1];
            v.z = acc[i][2] + bb[2]; v.w = acc[i][3] + bb[3];
            *(float4*)(og + (size_t)n * HD_ + tx * 4) = v;
        }
    } else {
        float* og = out + (size_t)hb * HD_ * N_;
#pragma unroll
        for (int j = 0; j < 4; j++) {
            int d = tx * 4 + j;
            float* row = og + (size_t)d * N_ + n0 + ty * 8;
#pragma unroll
            for (int i = 0; i < 8; i++) row[i] = acc[i][j] + bb[j];
        }
    }
}

// ---------------- kernel 2: E = Q K^T tiles + online row max/sum ----------------
// CTA: one (hb, n-block of 128). Loops m in tiles of 128. 8x8 micro-tiles.
__global__ __launch_bounds__(256, 2) void pass1_kernel()
{
    extern __shared__ float sm[];
    float* Qs = sm;                 // [64][132]  (Qs[d][n])
    float* Ks = sm + 64 * 132;      // [64][132]  (Ks[d][m])

    int hb  = blockIdx.y;
    int n0  = blockIdx.x * 128;
    int tid = threadIdx.x;
    int tx  = tid & 15;   // -> m (8 per thread)
    int ty  = tid >> 4;   // -> n (8 per thread)

    // load Q tile once (global layout [hb][d][n] -> coalesced float4 over n)
    {
        const float* qg = g_qT + (size_t)hb * HD_ * N_ + n0;
        int r  = tid >> 2;         // d: 0..63
        int c4 = tid & 3;
#pragma unroll
        for (int k = 0; k < 8; k++) {
            int c = (c4 + 4 * k) * 4;   // 0..124
            *(float4*)&Qs[r * 132 + c] = *(const float4*)(qg + (size_t)r * N_ + c);
        }
    }

    float run_max[8], run_sum[8];
#pragma unroll
    for (int i = 0; i < 8; i++) { run_max[i] = -3.0e38f; run_sum[i] = 0.f; }

    for (int m0 = 0; m0 < N_; m0 += 128) {
        __syncthreads();
        {
            const float* kg = g_kT + (size_t)hb * HD_ * N_ + m0;
            int r  = tid >> 2;
            int c4 = tid & 3;
#pragma unroll
            for (int k = 0; k < 8; k++) {
                int c = (c4 + 4 * k) * 4;
                *(float4*)&Ks[r * 132 + c] = *(const float4*)(kg + (size_t)r * N_ + c);
            }
        }
        __syncthreads();

        float acc[8][8];
#pragma unroll
        for (int i = 0; i < 8; i++)
#pragma unroll
            for (int j = 0; j < 8; j++) acc[i][j] = 0.f;

#pragma unroll 4
        for (int d = 0; d < 64; d++) {
            float4 a0 = *(float4*)&Qs[d * 132 + ty * 8];
            float4 a1 = *(float4*)&Qs[d * 132 + ty * 8 + 4];
            float4 b0 = *(float4*)&Ks[d * 132 + tx * 8];
            float4 b1 = *(float4*)&Ks[d * 132 + tx * 8 + 4];
            float aa[8] = {a0.x, a0.y, a0.z, a0.w, a1.x, a1.y, a1.z, a1.w};
            float bbv[8] = {b0.x, b0.y, b0.z, b0.w, b1.x, b1.y, b1.z, b1.w};
#pragma unroll
            for (int i = 0; i < 8; i++)
#pragma unroll
                for (int j = 0; j < 8; j++) acc[i][j] += aa[i] * bbv[j];
        }

        // write raw E tile
        float* Eg = g_E + (size_t)hb * N_ * N_ + (size_t)n0 * N_ + m0;
#pragma unroll
        for (int i = 0; i < 8; i++) {
            float* p = Eg + (size_t)(ty * 8 + i) * N_ + tx * 8;
            float4 v0, v1;
            v0.x = acc[i][0]; v0.y = acc[i][1]; v0.z = acc[i][2]; v0.w = acc[i][3];
            v1.x = acc[i][4]; v1.y = acc[i][5]; v1.z = acc[i][6]; v1.w = acc[i][7];
            *(float4*)p       = v0;
            *(float4*)(p + 4) = v1;
        }

        // online row max / sumexp (16-lane groups share a row; lanes 0-15 / 16-31)
#pragma unroll
        for (int i = 0; i < 8; i++) {
            float tm = acc[i][0];
#pragma unroll
            for (int j = 1; j < 8; j++) tm = fmaxf(tm, acc[i][j]);
#pragma unroll
            for (int s = 8; s; s >>= 1) tm = fmaxf(tm, __shfl_xor_sync(0xffffffffu, tm, s));
            float nm = fmaxf(run_max[i], tm);
            float ps = 0.f;
#pragma unroll
            for (int j = 0; j < 8; j++) ps += __expf(acc[i][j] - nm);
#pragma unroll
            for (int s = 8; s; s >>= 1) ps += __shfl_xor_sync(0xffffffffu, ps, s);
            run_sum[i] = run_sum[i] * __expf(run_max[i] - nm) + ps;
            run_max[i] = nm;
        }
    }

    if (tx == 0) {
#pragma unroll
        for (int i = 0; i < 8; i++) {
            g_rmax[hb * N_ + n0 + ty * 8 + i] = run_max[i];
            g_rsum[hb * N_ + n0 + ty * 8 + i] = run_sum[i];
        }
    }
}

// ---------------- kernel 3: Out = P^T V + gamma blend ----------------
// CTA: one (hb, m-block of 128). Streams n in chunks of 32.
__global__ __launch_bounds__(256) void pass2_kernel(
    const float* __restrict__ gamma, float* __restrict__ out)
{
    __shared__ float Ps[32][132];   // P[n][m]
    __shared__ float Vs[32][68];    // V[n][d]

    int hb  = blockIdx.y;
    int m0  = blockIdx.x * 128;
    int tid = threadIdx.x;
    int tx  = tid & 15;   // -> d (4 per thread)
    int ty  = tid >> 4;   // -> m (8 per thread)

    float acc[8][4];
#pragma unroll
    for (int i = 0; i < 8; i++)
#pragma unroll
        for (int j = 0; j < 4; j++) acc[i][j] = 0.f;

    for (int n0 = 0; n0 < N_; n0 += 32) {
        __syncthreads();
        {
            int r  = tid >> 3;   // 0..31 (n row)
            int c4 = tid & 7;
            float rmx = g_rmax[hb * N_ + n0 + r];
            float rin = 1.0f / g_rsum[hb * N_ + n0 + r];
            const float* Eg = g_E + (size_t)hb * N_ * N_ + (size_t)(n0 + r) * N_ + m0;
#pragma unroll
            for (int k = 0; k < 4; k++) {
                int c = (c4 + 8 * k) * 4;   // 0..124
                float4 e = *(const float4*)(Eg + c);
                float4 p;
                p.x = __expf(e.x - rmx) * rin;
                p.y = __expf(e.y - rmx) * rin;
                p.z = __expf(e.z - rmx) * rin;
                p.w = __expf(e.w - rmx) * rin;
                *(float4*)&Ps[r][c] = p;
            }
            const float* Vg = g_v + ((size_t)hb * N_ + n0 + r) * HD_;
#pragma unroll
            for (int k = 0; k < 2; k++) {
                int c = (c4 + 8 * k) * 4;   // 0..60
                *(float4*)&Vs[r][c] = *(const float4*)(Vg + c);
            }
        }
        __syncthreads();

#pragma unroll 8
        for (int n = 0; n < 32; n++) {
            float4 p0 = *(float4*)&Ps[n][ty * 8];
            float4 p1 = *(float4*)&Ps[n][ty * 8 + 4];
            float4 v4 = *(float4*)&Vs[n][tx * 4];
            float pp[8] = {p0.x, p0.y, p0.z, p0.w, p1.x, p1.y, p1.z, p1.w};
            float vv[4] = {v4.x, v4.y, v4.z, v4.w};
#pragma unroll
            for (int i = 0; i < 8; i++)
#pragma unroll
                for (int j = 0; j < 4; j++) acc[i][j] += pp[i] * vv[j];
        }
    }

    int h = hb >> 2;     // hb = h*B_ + b, B_=4
    int b = hb & 3;
    float g = gamma[h];
    float s = 1.0f / (1.0f + g);
    const float* ypg = g_yp + (size_t)b * N_ * HD_;
    float* og = out + (size_t)hb * N_ * HD_;
#pragma unroll
    for (int i = 0; i < 8; i++) {
        int m = m0 + ty * 8 + i;
        float4 y4 = *(const float4*)(ypg + (size_t)m * HD_ + tx * 4);
        float4 o;
        o.x = (g * acc[i][0] + y4.x) * s;
        o.y = (g * acc[i][1] + y4.y) * s;
        o.z = (g * acc[i][2] + y4.z) * s;
        o.w = (g * acc[i][3] + y4.w) * s;
        *(float4*)(og + (size_t)m * HD_ + tx * 4) = o;
    }
}

// ---------------- launch ----------------
extern "C" void kernel_launch(void* const* d_in, const int* in_sizes, int n_in,
                              void* d_out, int out_size)
{
    const float* x  = (const float*)d_in[0];
    const float* y  = (const float*)d_in[1];
    const float* Wq = (const float*)d_in[2];
    const float* bq = (const float*)d_in[3];
    const float* Wk = (const float*)d_in[4];
    const float* bk = (const float*)d_in[5];
    const float* Wv = (const float*)d_in[6];
    const float* bv = (const float*)d_in[7];
    const float* Wp = (const float*)d_in[8];
    const float* gm = (const float*)d_in[9];
    float* out = (float*)d_out;

    float *qT, *kT, *v, *yp;
    cudaGetSymbolAddress((void**)&qT, g_qT);
    cudaGetSymbolAddress((void**)&kT, g_kT);
    cudaGetSymbolAddress((void**)&v,  g_v);
    cudaGetSymbolAddress((void**)&yp, g_yp);

    const int smem1 = 64 * 132 * 4 * 2;   // 67584 bytes
    cudaFuncSetAttribute(pass1_kernel, cudaFuncAttributeMaxDynamicSharedMemorySize, smem1);

    dim3 blk(256);
    proj_kernel<<<dim3(16, 8, 4), blk>>>(Wq, bq, x, qT, 1);
    proj_kernel<<<dim3(16, 8, 4), blk>>>(Wk, bk, y, kT, 1);
    proj_kernel<<<dim3(16, 8, 4), blk>>>(Wv, bv, y, v,  0);
    proj_kernel<<<dim3(16, 1, 4), blk>>>(Wp, nullptr, y, yp, 0);

    pass1_kernel<<<dim3(16, 32), blk, smem1>>>();
    pass2_kernel<<<dim3(16, 32), blk>>>(gm, out);
}

// round 6
// speedup vs baseline: 1.0240x; 1.0240x over previous
#include <cuda_runtime.h>

#define H_  8
#define B_  4
#define C_  256
#define N_  2048
#define HD_ 64
#define O_  512
#define HB_ 32   // H_*B_

// ---------------- scratch (device globals; no allocations allowed) ----------------
__device__ float g_qT[HB_ * HD_ * N_];         // [hb][d][n]   (transposed for pass1)
__device__ float g_kT[HB_ * HD_ * N_];         // [hb][d][n]
__device__ float g_v [HB_ * N_ * HD_];         // [hb][n][d]
__device__ float g_yp[B_ * N_ * HD_];          // [b][n][d]
__device__ float g_E [(size_t)HB_ * N_ * N_];  // [hb][n][m]  raw logits, fp32 (536 MB)
__device__ float g_rmax[HB_ * N_];             // row max over m
__device__ float g_rsum[HB_ * N_];             // row sum of exp(E - rmax)

// ---------------- packed fp32x2 helpers (FFMA2 on sm_103a) ----------------
__device__ __forceinline__ unsigned long long ffma2(unsigned long long a,
                                                    unsigned long long b,
                                                    unsigned long long c)
{
    unsigned long long d;
    asm("fma.rn.f32x2 %0, %1, %2, %3;" : "=l"(d) : "l"(a), "l"(b), "l"(c));
    return d;
}
__device__ __forceinline__ unsigned long long dup2(float x)
{
    unsigned long long d;
    unsigned u = __float_as_uint(x);
    asm("mov.b64 %0, {%1, %2};" : "=l"(d) : "r"(u), "r"(u));
    return d;
}
__device__ __forceinline__ float2 unpk(unsigned long long p)
{
    unsigned lo, hi;
    asm("mov.b64 {%0, %1}, %2;" : "=r"(lo), "=r"(hi) : "l"(p));
    float2 r;
    r.x = __uint_as_float(lo);
    r.y = __uint_as_float(hi);
    return r;
}

// ---------------- kernel 1: ALL 1x1 conv projections in one launch ----------------
// grid: (16 n-blocks, 25 o-blocks, 4 batch). y in [0,8)=Q, [8,16)=K, [16,24)=V, 24=yp.
// out tile: 64 (o) x 128 (n) per CTA; K = C = 256 in chunks of 32.
__global__ __launch_bounds__(256) void proj_all_kernel(
    const float* __restrict__ Wq, const float* __restrict__ bq,
    const float* __restrict__ Wk, const float* __restrict__ bk,
    const float* __restrict__ Wv, const float* __restrict__ bv,
    const float* __restrict__ Wp,
    const float* __restrict__ x, const float* __restrict__ y,
    float* __restrict__ qT, float* __restrict__ kT,
    float* __restrict__ v,  float* __restrict__ yp)
{
    __shared__ float Ws[32][68];    // [c'][o]
    __shared__ float Xs[32][132];   // [c'][n]

    int which = blockIdx.y;
    const float *W, *bias, *in;
    float* out;
    int transposed, oh;
    if (which < 8)       { W = Wq; bias = bq;      in = x; out = qT; transposed = 1; oh = which; }
    else if (which < 16) { W = Wk; bias = bk;      in = y; out = kT; transposed = 1; oh = which - 8; }
    else if (which < 24) { W = Wv; bias = bv;      in = y; out = v;  transposed = 0; oh = which - 16; }
    else                 { W = Wp; bias = nullptr; in = y; out = yp; transposed = 0; oh = 0; }

    int b   = blockIdx.z;
    int o0  = oh * 64;
    int n0  = blockIdx.x * 128;
    int tid = threadIdx.x;
    int tx  = tid & 15;   // -> d (4 per thread)
    int ty  = tid >> 4;   // -> n (8 per thread, paired)

    unsigned long long acc2[4][4];   // [n-pair][d]
#pragma unroll
    for (int i = 0; i < 4; i++)
#pragma unroll
        for (int j = 0; j < 4; j++) acc2[i][j] = 0ull;

    const float* inb = in + (size_t)b * C_ * N_;

    for (int c0 = 0; c0 < C_; c0 += 32) {
        __syncthreads();
        // W tile: Ws[c'][d]
        {
            int cc = tid & 31;
            int d0 = tid >> 5;
#pragma unroll
            for (int k = 0; k < 8; k++) {
                int d = d0 + 8 * k;
                Ws[cc][d] = W[(size_t)(o0 + d) * C_ + c0 + cc];
            }
        }
        // X tile: Xs[c'][n]  (float4, coalesced over n)
        {
            int n4  = tid & 31;
            int c0p = tid >> 5;
#pragma unroll
            for (int k = 0; k < 4; k++) {
                int cp = c0p + 8 * k;
                *(float4*)&Xs[cp][n4 * 4] =
                    *(const float4*)(inb + (size_t)(c0 + cp) * N_ + n0 + n4 * 4);
            }
        }
        __syncthreads();
#pragma unroll 4
        for (int cp = 0; cp < 32; cp++) {
            const float* xrow = &Xs[cp][ty * 8];
            unsigned long long a0 = *(const unsigned long long*)(xrow + 0);
            unsigned long long a1 = *(const unsigned long long*)(xrow + 2);
            unsigned long long a2 = *(const unsigned long long*)(xrow + 4);
            unsigned long long a3 = *(const unsigned long long*)(xrow + 6);
            const float* wrow = &Ws[cp][tx * 4];
#pragma unroll
            for (int j = 0; j < 4; j++) {
                unsigned long long w2 = dup2(wrow[j]);
                acc2[0][j] = ffma2(a0, w2, acc2[0][j]);
                acc2[1][j] = ffma2(a1, w2, acc2[1][j]);
                acc2[2][j] = ffma2(a2, w2, acc2[2][j]);
                acc2[3][j] = ffma2(a3, w2, acc2[3][j]);
            }
        }
    }

    float acc[8][4];
#pragma unroll
    for (int ip = 0; ip < 4; ip++)
#pragma unroll
        for (int j = 0; j < 4; j++) {
            float2 f = unpk(acc2[ip][j]);
            acc[2 * ip][j]     = f.x;
            acc[2 * ip + 1][j] = f.y;
        }

    float bb[4] = {0.f, 0.f, 0.f, 0.f};
    if (bias) {
        float4 b4 = *(const float4*)(bias + o0 + tx * 4);
        bb[0] = b4.x; bb[1] = b4.y; bb[2] = b4.z; bb[3] = b4.w;
    }

    int hb = oh * B_ + b;
    if (!transposed) {
        float* og = out + (size_t)hb * N_ * HD_;
#pragma unroll
        for (int i = 0; i < 8; i++) {
            int n = n0 + ty * 8 + i;
            float4 o4;
            o4.x = acc[i][0] + bb[0]; o4.y = acc[i][1] + bb[1];
            o4.z = acc[i][2] + bb[2]; o4.w = acc[i][3] + bb[3];
            *(float4*)(og + (size_t)n * HD_ + tx * 4) = o4;
        }
    } else {
        float* og = out + (size_t)hb * HD_ * N_;
#pragma unroll
        for (int j = 0; j < 4; j++) {
            int d = tx * 4 + j;
            float* row = og + (size_t)d * N_ + n0 + ty * 8;
#pragma unroll
            for (int i = 0; i < 8; i++) row[i] = acc[i][j] + bb[j];
        }
    }
}

// ---------------- kernel 2: E = Q K^T tiles + online row max/sum ----------------
// CTA: one (hb, n-block of 128). Loops m in tiles of 128. 8x8 micro-tiles, FFMA2.
__global__ __launch_bounds__(256, 2) void pass1_kernel()
{
    extern __shared__ float sm[];
    float* Qs = sm;                 // [64][132]  (Qs[d][n])
    float* Ks = sm + 64 * 132;      // [64][132]  (Ks[d][m])

    int hb  = blockIdx.y;
    int n0  = blockIdx.x * 128;
    int tid = threadIdx.x;
    int tx  = tid & 15;   // -> m (8 per thread)
    int ty  = tid >> 4;   // -> n (8 per thread, paired)

    // load Q tile once (global layout [hb][d][n] -> coalesced float4 over n)
    {
        const float* qg = g_qT + (size_t)hb * HD_ * N_ + n0;
        int r  = tid >> 2;
        int c4 = tid & 3;
#pragma unroll
        for (int k = 0; k < 8; k++) {
            int c = (c4 + 4 * k) * 4;
            *(float4*)&Qs[r * 132 + c] = *(const float4*)(qg + (size_t)r * N_ + c);
        }
    }

    float run_max[8], run_sum[8];
#pragma unroll
    for (int i = 0; i < 8; i++) { run_max[i] = -3.0e38f; run_sum[i] = 0.f; }

    for (int m0 = 0; m0 < N_; m0 += 128) {
        __syncthreads();
        {
            const float* kg = g_kT + (size_t)hb * HD_ * N_ + m0;
            int r  = tid >> 2;
            int c4 = tid & 3;
#pragma unroll
            for (int k = 0; k < 8; k++) {
                int c = (c4 + 4 * k) * 4;
                *(float4*)&Ks[r * 132 + c] = *(const float4*)(kg + (size_t)r * N_ + c);
            }
        }
        __syncthreads();

        unsigned long long acc2[4][8];   // [n-pair][m]
#pragma unroll
        for (int i = 0; i < 4; i++)
#pragma unroll
            for (int j = 0; j < 8; j++) acc2[i][j] = 0ull;

#pragma unroll 4
        for (int d = 0; d < 64; d++) {
            const float* qrow = &Qs[d * 132 + ty * 8];
            unsigned long long a0 = *(const unsigned long long*)(qrow + 0);
            unsigned long long a1 = *(const unsigned long long*)(qrow + 2);
            unsigned long long a2 = *(const unsigned long long*)(qrow + 4);
            unsigned long long a3 = *(const unsigned long long*)(qrow + 6);
            const float* krow = &Ks[d * 132 + tx * 8];
#pragma unroll
            for (int j = 0; j < 8; j++) {
                unsigned long long b2 = dup2(krow[j]);
                acc2[0][j] = ffma2(a0, b2, acc2[0][j]);
                acc2[1][j] = ffma2(a1, b2, acc2[1][j]);
                acc2[2][j] = ffma2(a2, b2, acc2[2][j]);
                acc2[3][j] = ffma2(a3, b2, acc2[3][j]);
            }
        }

        float acc[8][8];
#pragma unroll
        for (int ip = 0; ip < 4; ip++)
#pragma unroll
            for (int j = 0; j < 8; j++) {
                float2 f = unpk(acc2[ip][j]);
                acc[2 * ip][j]     = f.x;
                acc[2 * ip + 1][j] = f.y;
            }

        // write raw E tile
        float* Eg = g_E + (size_t)hb * N_ * N_ + (size_t)n0 * N_ + m0;
#pragma unroll
        for (int i = 0; i < 8; i++) {
            float* p = Eg + (size_t)(ty * 8 + i) * N_ + tx * 8;
            float4 v0, v1;
            v0.x = acc[i][0]; v0.y = acc[i][1]; v0.z = acc[i][2]; v0.w = acc[i][3];
            v1.x = acc[i][4]; v1.y = acc[i][5]; v1.z = acc[i][6]; v1.w = acc[i][7];
            *(float4*)p       = v0;
            *(float4*)(p + 4) = v1;
        }

        // online row max / sumexp (16-lane groups share a row)
#pragma unroll
        for (int i = 0; i < 8; i++) {
            float tm = acc[i][0];
#pragma unroll
            for (int j = 1; j < 8; j++) tm = fmaxf(tm, acc[i][j]);
#pragma unroll
            for (int s = 8; s; s >>= 1) tm = fmaxf(tm, __shfl_xor_sync(0xffffffffu, tm, s));
            float nm = fmaxf(run_max[i], tm);
            float ps = 0.f;
#pragma unroll
            for (int j = 0; j < 8; j++) ps += __expf(acc[i][j] - nm);
#pragma unroll
            for (int s = 8; s; s >>= 1) ps += __shfl_xor_sync(0xffffffffu, ps, s);
            run_sum[i] = run_sum[i] * __expf(run_max[i] - nm) + ps;
            run_max[i] = nm;
        }
    }

    if (tx == 0) {
#pragma unroll
        for (int i = 0; i < 8; i++) {
            g_rmax[hb * N_ + n0 + ty * 8 + i] = run_max[i];
            g_rsum[hb * N_ + n0 + ty * 8 + i] = run_sum[i];
        }
    }
}

// ---------------- kernel 3: Out = P^T V + gamma blend ----------------
// CTA: one (hb, m-block of 128). Streams n in chunks of 32. FFMA2 inner.
__global__ __launch_bounds__(256) void pass2_kernel(
    const float* __restrict__ gamma, float* __restrict__ out)
{
    __shared__ float Ps[32][132];   // P[n][m]
    __shared__ float Vs[32][68];    // V[n][d]

    int hb  = blockIdx.y;
    int m0  = blockIdx.x * 128;
    int tid = threadIdx.x;
    int tx  = tid & 15;   // -> d (4 per thread)
    int ty  = tid >> 4;   // -> m (8 per thread, paired)

    unsigned long long acc2[4][4];   // [m-pair][d]
#pragma unroll
    for (int i = 0; i < 4; i++)
#pragma unroll
        for (int j = 0; j < 4; j++) acc2[i][j] = 0ull;

    for (int n0 = 0; n0 < N_; n0 += 32) {
        __syncthreads();
        {
            int r  = tid >> 3;   // 0..31 (n row)
            int c4 = tid & 7;
            float rmx = g_rmax[hb * N_ + n0 + r];
            float rin = 1.0f / g_rsum[hb * N_ + n0 + r];
            const float* Eg = g_E + (size_t)hb * N_ * N_ + (size_t)(n0 + r) * N_ + m0;
#pragma unroll
            for (int k = 0; k < 4; k++) {
                int c = (c4 + 8 * k) * 4;
                float4 e = *(const float4*)(Eg + c);
                float4 p;
                p.x = __expf(e.x - rmx) * rin;
                p.y = __expf(e.y - rmx) * rin;
                p.z = __expf(e.z - rmx) * rin;
                p.w = __expf(e.w - rmx) * rin;
                *(float4*)&Ps[r][c] = p;
            }
            const float* Vg = g_v + ((size_t)hb * N_ + n0 + r) * HD_;
#pragma unroll
            for (int k = 0; k < 2; k++) {
                int c = (c4 + 8 * k) * 4;
                if (c < 64)
                    *(float4*)&Vs[r][c] = *(const float4*)(Vg + c);
            }
        }
        __syncthreads();

#pragma unroll 8
        for (int n = 0; n < 32; n++) {
            const float* prow = &Ps[n][ty * 8];
            unsigned long long p0 = *(const unsigned long long*)(prow + 0);
            unsigned long long p1 = *(const unsigned long long*)(prow + 2);
            unsigned long long p2 = *(const unsigned long long*)(prow + 4);
            unsigned long long p3 = *(const unsigned long long*)(prow + 6);
            const float* vrow = &Vs[n][tx * 4];
#pragma unroll
            for (int j = 0; j < 4; j++) {
                unsigned long long v2 = dup2(vrow[j]);
                acc2[0][j] = ffma2(p0, v2, acc2[0][j]);
                acc2[1][j] = ffma2(p1, v2, acc2[1][j]);
                acc2[2][j] = ffma2(p2, v2, acc2[2][j]);
                acc2[3][j] = ffma2(p3, v2, acc2[3][j]);
            }
        }
    }

    float acc[8][4];
#pragma unroll
    for (int ip = 0; ip < 4; ip++)
#pragma unroll
        for (int j = 0; j < 4; j++) {
            float2 f = unpk(acc2[ip][j]);
            acc[2 * ip][j]     = f.x;
            acc[2 * ip + 1][j] = f.y;
        }

    int h = hb >> 2;     // hb = h*B_ + b, B_=4
    int b = hb & 3;
    float g = gamma[h];
    float s = 1.0f / (1.0f + g);
    const float* ypg = g_yp + (size_t)b * N_ * HD_;
    float* og = out + (size_t)hb * N_ * HD_;
#pragma unroll
    for (int i = 0; i < 8; i++) {
        int m = m0 + ty * 8 + i;
        float4 y4 = *(const float4*)(ypg + (size_t)m * HD_ + tx * 4);
        float4 o;
        o.x = (g * acc[i][0] + y4.x) * s;
        o.y = (g * acc[i][1] + y4.y) * s;
        o.z = (g * acc[i][2] + y4.z) * s;
        o.w = (g * acc[i][3] + y4.w) * s;
        *(float4*)(og + (size_t)m * HD_ + tx * 4) = o;
    }
}

// ---------------- launch ----------------
extern "C" void kernel_launch(void* const* d_in, const int* in_sizes, int n_in,
                              void* d_out, int out_size)
{
    const float* x  = (const float*)d_in[0];
    const float* y  = (const float*)d_in[1];
    const float* Wq = (const float*)d_in[2];
    const float* bq = (const float*)d_in[3];
    const float* Wk = (const float*)d_in[4];
    const float* bk = (const float*)d_in[5];
    const float* Wv = (const float*)d_in[6];
    const float* bv = (const float*)d_in[7];
    const float* Wp = (const float*)d_in[8];
    const float* gm = (const float*)d_in[9];
    float* out = (float*)d_out;

    float *qT, *kT, *v, *yp;
    cudaGetSymbolAddress((void**)&qT, g_qT);
    cudaGetSymbolAddress((void**)&kT, g_kT);
    cudaGetSymbolAddress((void**)&v,  g_v);
    cudaGetSymbolAddress((void**)&yp, g_yp);

    const int smem1 = 64 * 132 * 4 * 2;   // 67584 bytes
    cudaFuncSetAttribute(pass1_kernel, cudaFuncAttributeMaxDynamicSharedMemorySize, smem1);

    dim3 blk(256);
    proj_all_kernel<<<dim3(16, 25, 4), blk>>>(Wq, bq, Wk, bk, Wv, bv, Wp,
                                              x, y, qT, kT, v, yp);
    pass1_kernel<<<dim3(16, 32), blk, smem1>>>();
    pass2_kernel<<<dim3(16, 32), blk>>>(gm, out);
}

// round 7
// speedup vs baseline: 1.4246x; 1.3912x over previous
#include <cuda_runtime.h>
#include <cuda_bf16.h>
#include <cstdint>

#define H_  8
#define B_  4
#define C_  256
#define N_  2048
#define HD_ 64
#define HB_ 32   // H_*B_

// ---------------- scratch (device globals; no allocations allowed) ----------------
__device__ __nv_bfloat16 g_qh[HB_ * N_ * HD_];   // [hb][n][d] hi
__device__ __nv_bfloat16 g_ql[HB_ * N_ * HD_];   // [hb][n][d] lo
__device__ __nv_bfloat16 g_kh[HB_ * N_ * HD_];   // [hb][m][d] hi
__device__ __nv_bfloat16 g_kl[HB_ * N_ * HD_];   // [hb][m][d] lo
__device__ __nv_bfloat16 g_vth[HB_ * HD_ * N_];  // [hb][d][n] hi (transposed V)
__device__ __nv_bfloat16 g_vtl[HB_ * HD_ * N_];  // [hb][d][n] lo
__device__ float g_yp[B_ * N_ * HD_];            // [b][n][d]
__device__ float g_E [(size_t)HB_ * N_ * N_];    // [hb][n][m] raw logits fp32
__device__ float g_rmax[HB_ * N_];
__device__ float g_rsum[HB_ * N_];

// ---------------- helpers ----------------
__device__ __forceinline__ unsigned long long ffma2(unsigned long long a,
                                                    unsigned long long b,
                                                    unsigned long long c)
{
    unsigned long long d;
    asm("fma.rn.f32x2 %0, %1, %2, %3;" : "=l"(d) : "l"(a), "l"(b), "l"(c));
    return d;
}
__device__ __forceinline__ unsigned long long dup2(float x)
{
    unsigned long long d;
    unsigned u = __float_as_uint(x);
    asm("mov.b64 %0, {%1, %2};" : "=l"(d) : "r"(u), "r"(u));
    return d;
}
__device__ __forceinline__ float2 unpk(unsigned long long p)
{
    unsigned lo, hi;
    asm("mov.b64 {%0, %1}, %2;" : "=r"(lo), "=r"(hi) : "l"(p));
    float2 r;
    r.x = __uint_as_float(lo);
    r.y = __uint_as_float(hi);
    return r;
}
__device__ __forceinline__ uint32_t pk2(__nv_bfloat16 a, __nv_bfloat16 b)
{
    return (uint32_t)__bfloat16_as_ushort(a) | ((uint32_t)__bfloat16_as_ushort(b) << 16);
}
__device__ __forceinline__ void split_bf(float v, __nv_bfloat16& h, __nv_bfloat16& l)
{
    h = __float2bfloat16(v);
    l = __float2bfloat16(v - __bfloat162float(h));
}
__device__ __forceinline__ void mma_bf16(float c[4],
                                         uint32_t a0, uint32_t a1, uint32_t a2, uint32_t a3,
                                         uint32_t b0, uint32_t b1)
{
    asm volatile(
        "mma.sync.aligned.m16n8k16.row.col.f32.bf16.bf16.f32 "
        "{%0,%1,%2,%3}, {%4,%5,%6,%7}, {%8,%9}, {%0,%1,%2,%3};"
        : "+f"(c[0]), "+f"(c[1]), "+f"(c[2]), "+f"(c[3])
        : "r"(a0), "r"(a1), "r"(a2), "r"(a3), "r"(b0), "r"(b1));
}

// ---------------- kernel 1: ALL 1x1 conv projections ----------------
// grid (16 nblk, 25 oblk, 4 batch). y: [0,8)=Q, [8,16)=K, [16,24)=V, 24=yp.
__global__ __launch_bounds__(256) void proj_all_kernel(
    const float* __restrict__ Wq, const float* __restrict__ bq,
    const float* __restrict__ Wk, const float* __restrict__ bk,
    const float* __restrict__ Wv, const float* __restrict__ bv,
    const float* __restrict__ Wp,
    const float* __restrict__ x, const float* __restrict__ y)
{
    __shared__ float Ws[32][68];
    __shared__ float Xs[32][132];

    int which = blockIdx.y;
    const float *W, *bias, *in;
    int oh;
    if (which < 8)       { W = Wq; bias = bq;      in = x; oh = which; }
    else if (which < 16) { W = Wk; bias = bk;      in = y; oh = which - 8; }
    else if (which < 24) { W = Wv; bias = bv;      in = y; oh = which - 16; }
    else                 { W = Wp; bias = nullptr; in = y; oh = 0; }

    int b   = blockIdx.z;
    int o0  = oh * 64;
    int n0  = blockIdx.x * 128;
    int tid = threadIdx.x;
    int tx  = tid & 15;   // -> d (4 per thread)
    int ty  = tid >> 4;   // -> n (8 per thread)

    unsigned long long acc2[4][4];
#pragma unroll
    for (int i = 0; i < 4; i++)
#pragma unroll
        for (int j = 0; j < 4; j++) acc2[i][j] = 0ull;

    const float* inb = in + (size_t)b * C_ * N_;

    for (int c0 = 0; c0 < C_; c0 += 32) {
        __syncthreads();
        {
            int cc = tid & 31;
            int d0 = tid >> 5;
#pragma unroll
            for (int k = 0; k < 8; k++) {
                int d = d0 + 8 * k;
                Ws[cc][d] = W[(size_t)(o0 + d) * C_ + c0 + cc];
            }
        }
        {
            int n4  = tid & 31;
            int c0p = tid >> 5;
#pragma unroll
            for (int k = 0; k < 4; k++) {
                int cp = c0p + 8 * k;
                *(float4*)&Xs[cp][n4 * 4] =
                    *(const float4*)(inb + (size_t)(c0 + cp) * N_ + n0 + n4 * 4);
            }
        }
        __syncthreads();
#pragma unroll 4
        for (int cp = 0; cp < 32; cp++) {
            const float* xrow = &Xs[cp][ty * 8];
            unsigned long long a0 = *(const unsigned long long*)(xrow + 0);
            unsigned long long a1 = *(const unsigned long long*)(xrow + 2);
            unsigned long long a2 = *(const unsigned long long*)(xrow + 4);
            unsigned long long a3 = *(const unsigned long long*)(xrow + 6);
            const float* wrow = &Ws[cp][tx * 4];
#pragma unroll
            for (int j = 0; j < 4; j++) {
                unsigned long long w2 = dup2(wrow[j]);
                acc2[0][j] = ffma2(a0, w2, acc2[0][j]);
                acc2[1][j] = ffma2(a1, w2, acc2[1][j]);
                acc2[2][j] = ffma2(a2, w2, acc2[2][j]);
                acc2[3][j] = ffma2(a3, w2, acc2[3][j]);
            }
        }
    }

    float acc[8][4];
#pragma unroll
    for (int ip = 0; ip < 4; ip++)
#pragma unroll
        for (int j = 0; j < 4; j++) {
            float2 f = unpk(acc2[ip][j]);
            acc[2 * ip][j]     = f.x;
            acc[2 * ip + 1][j] = f.y;
        }

    float bb[4] = {0.f, 0.f, 0.f, 0.f};
    if (bias) {
        float4 b4 = *(const float4*)(bias + o0 + tx * 4);
        bb[0] = b4.x; bb[1] = b4.y; bb[2] = b4.z; bb[3] = b4.w;
    }

    int hb = oh * B_ + b;
    if (which >= 24) {
        // yp fp32 [b][n][d]
#pragma unroll
        for (int i = 0; i < 8; i++) {
            int n = n0 + ty * 8 + i;
            float4 o4;
            o4.x = acc[i][0]; o4.y = acc[i][1]; o4.z = acc[i][2]; o4.w = acc[i][3];
            *(float4*)(g_yp + ((size_t)b * N_ + n) * HD_ + tx * 4) = o4;
        }
    } else if (which < 16) {
        // Q / K: bf16 hi/lo, [hb][n][d]
        __nv_bfloat16* oh_ = (which < 8) ? g_qh : g_kh;
        __nv_bfloat16* ol_ = (which < 8) ? g_ql : g_kl;
        size_t base = (size_t)hb * N_ * HD_;
#pragma unroll
        for (int i = 0; i < 8; i++) {
            int n = n0 + ty * 8 + i;
            __nv_bfloat16 h[4], l[4];
#pragma unroll
            for (int j = 0; j < 4; j++) split_bf(acc[i][j] + bb[j], h[j], l[j]);
            uint2 hv = {pk2(h[0], h[1]), pk2(h[2], h[3])};
            uint2 lv = {pk2(l[0], l[1]), pk2(l[2], l[3])};
            *(uint2*)&oh_[base + (size_t)n * HD_ + tx * 4] = hv;
            *(uint2*)&ol_[base + (size_t)n * HD_ + tx * 4] = lv;
        }
    } else {
        // V transposed: bf16 hi/lo, [hb][d][n]
        size_t base = (size_t)hb * HD_ * N_;
#pragma unroll
        for (int j = 0; j < 4; j++) {
            int d = tx * 4 + j;
            __nv_bfloat16 h[8], l[8];
#pragma unroll
            for (int i = 0; i < 8; i++) split_bf(acc[i][j] + bb[j], h[i], l[i]);
            uint4 hv = {pk2(h[0], h[1]), pk2(h[2], h[3]), pk2(h[4], h[5]), pk2(h[6], h[7])};
            uint4 lv = {pk2(l[0], l[1]), pk2(l[2], l[3]), pk2(l[4], l[5]), pk2(l[6], l[7])};
            *(uint4*)&g_vth[base + (size_t)d * N_ + n0 + ty * 8] = hv;
            *(uint4*)&g_vtl[base + (size_t)d * N_ + n0 + ty * 8] = lv;
        }
    }
}

// ---------------- kernel 2: E = Q K^T via HMMA (split bf16) + row stats ----------------
// CTA: (hb, n-block 128). m-loop in 128 tiles. Warp tile 16(n) x 128(m).
// SMEM tiles: rows of [64 hi | 64 lo] bf16, stride 136 elems (272B, conflict-free frags).
#define P1_STRIDE 136
__global__ __launch_bounds__(256, 2) void pass1_kernel()
{
    extern __shared__ __nv_bfloat16 sm1[];
    __nv_bfloat16* As = sm1;                   // [128][136]
    __nv_bfloat16* Bs = sm1 + 128 * P1_STRIDE; // [128][136]

    int hb  = blockIdx.y;
    int n0  = blockIdx.x * 128;
    int tid = threadIdx.x;
    int w   = tid >> 5;
    int t   = tid & 31;
    int g   = t >> 2;   // 0..7
    int c   = t & 3;    // 0..3

    // load A (Q tile) once: hi -> cols [0,64), lo -> cols [64,128)
    {
        const uint4* qh = (const uint4*)(g_qh + (size_t)(hb * N_ + n0) * HD_);
        const uint4* ql = (const uint4*)(g_ql + (size_t)(hb * N_ + n0) * HD_);
#pragma unroll
        for (int it = 0; it < 8; it++) {
            int lin = tid + 256 * it;       // 0..2047
            int row = lin >> 4, seg = lin & 15;
            uint4 v = (seg < 8) ? qh[row * 8 + seg] : ql[row * 8 + (seg - 8)];
            int col = (seg < 8) ? seg * 8 : 64 + (seg - 8) * 8;
            *(uint4*)&As[row * P1_STRIDE + col] = v;
        }
    }

    float run_max[2] = {-3.0e38f, -3.0e38f};
    float run_sum[2] = {0.f, 0.f};

    const int a_off[3] = {0, 64, 0};   // QhKh, QlKh, QhKl
    const int b_off[3] = {0, 0, 64};

    for (int m0 = 0; m0 < N_; m0 += 128) {
        __syncthreads();
        {
            const uint4* kh = (const uint4*)(g_kh + (size_t)(hb * N_ + m0) * HD_);
            const uint4* kl = (const uint4*)(g_kl + (size_t)(hb * N_ + m0) * HD_);
#pragma unroll
            for (int it = 0; it < 8; it++) {
                int lin = tid + 256 * it;
                int row = lin >> 4, seg = lin & 15;
                uint4 v = (seg < 8) ? kh[row * 8 + seg] : kl[row * 8 + (seg - 8)];
                int col = (seg < 8) ? seg * 8 : 64 + (seg - 8) * 8;
                *(uint4*)&Bs[row * P1_STRIDE + col] = v;
            }
        }
        __syncthreads();

        float acc[16][4];
#pragma unroll
        for (int j = 0; j < 16; j++)
#pragma unroll
            for (int q = 0; q < 4; q++) acc[j][q] = 0.f;

#pragma unroll
        for (int s = 0; s < 12; s++) {
            int grp = s >> 2;
            int ka = a_off[grp] + (s & 3) * 16 + 2 * c;
            int kb = b_off[grp] + (s & 3) * 16 + 2 * c;
            const __nv_bfloat16* arow = As + (16 * w + g) * P1_STRIDE;
            uint32_t a0 = *(const uint32_t*)(arow + ka);
            uint32_t a1 = *(const uint32_t*)(arow + 8 * P1_STRIDE + ka);
            uint32_t a2 = *(const uint32_t*)(arow + ka + 8);
            uint32_t a3 = *(const uint32_t*)(arow + 8 * P1_STRIDE + ka + 8);
#pragma unroll
            for (int j = 0; j < 16; j++) {
                const __nv_bfloat16* brow = Bs + (8 * j + g) * P1_STRIDE;
                uint32_t b0 = *(const uint32_t*)(brow + kb);
                uint32_t b1 = *(const uint32_t*)(brow + kb + 8);
                mma_bf16(acc[j], a0, a1, a2, a3, b0, b1);
            }
        }

        // online row stats (thread owns rows g, g+8 of warp's 16; quad reduce)
#pragma unroll
        for (int half = 0; half < 2; half++) {
            float tm = -3.0e38f;
#pragma unroll
            for (int j = 0; j < 16; j++)
                tm = fmaxf(tm, fmaxf(acc[j][2 * half], acc[j][2 * half + 1]));
            tm = fmaxf(tm, __shfl_xor_sync(0xffffffffu, tm, 1));
            tm = fmaxf(tm, __shfl_xor_sync(0xffffffffu, tm, 2));
            float nm = fmaxf(run_max[half], tm);
            float ps = 0.f;
#pragma unroll
            for (int j = 0; j < 16; j++)
                ps += __expf(acc[j][2 * half] - nm) + __expf(acc[j][2 * half + 1] - nm);
            ps += __shfl_xor_sync(0xffffffffu, ps, 1);
            ps += __shfl_xor_sync(0xffffffffu, ps, 2);
            run_sum[half] = run_sum[half] * __expf(run_max[half] - nm) + ps;
            run_max[half] = nm;
        }

        // store raw E tile
        float* Eg = g_E + (size_t)hb * N_ * N_ + (size_t)(n0 + 16 * w) * N_ + m0;
#pragma unroll
        for (int j = 0; j < 16; j++) {
            float2 v0 = {acc[j][0], acc[j][1]};
            float2 v1 = {acc[j][2], acc[j][3]};
            *(float2*)(Eg + (size_t)g * N_ + 8 * j + 2 * c)       = v0;
            *(float2*)(Eg + (size_t)(g + 8) * N_ + 8 * j + 2 * c) = v1;
        }
    }

    if (c == 0) {
        int n = n0 + 16 * w + g;
        g_rmax[hb * N_ + n]     = run_max[0];
        g_rsum[hb * N_ + n]     = run_sum[0];
        g_rmax[hb * N_ + n + 8] = run_max[1];
        g_rsum[hb * N_ + n + 8] = run_sum[1];
    }
}

// ---------------- kernel 3: Out = P^T V via HMMA + gamma blend ----------------
// CTA: (hb, m-block 128). n-chunks of 32. K interleaved: k=2n -> Ph, k=2n+1 -> Pl.
// B pass A: Vt1 = [Vh,Vh]; pass B: Vt2 = [Vl,Vl]  => exact (Ph+Pl)(Vh+Vl).
#define P2_STRIDE 72
__global__ __launch_bounds__(256, 2) void pass2_kernel(
    const float* __restrict__ gamma, float* __restrict__ out)
{
    __shared__ __nv_bfloat16 Pt [128 * P2_STRIDE];  // [m][64 interleaved k]
    __shared__ __nv_bfloat16 Vt1[64 * P2_STRIDE];   // [d][64]  (Vh dup)
    __shared__ __nv_bfloat16 Vt2[64 * P2_STRIDE];   // [d][64]  (Vl dup)

    int hb  = blockIdx.y;
    int m0  = blockIdx.x * 128;
    int tid = threadIdx.x;
    int w   = tid >> 5;
    int t   = tid & 31;
    int g   = t >> 2;
    int c   = t & 3;
    int r   = tid >> 3;   // 0..31 load-phase n-row
    int c8  = tid & 7;

    float acc[8][4];
#pragma unroll
    for (int j = 0; j < 8; j++)
#pragma unroll
        for (int q = 0; q < 4; q++) acc[j][q] = 0.f;

    for (int n0 = 0; n0 < N_; n0 += 32) {
        __syncthreads();
        // build Vt1/Vt2 (duplicated bf16 pairs)
        {
#pragma unroll
            for (int it = 0; it < 4; it++) {
                int lin = tid + 256 * it;   // 0..1023
                int d = lin >> 4, i = lin & 15;
                uint32_t v = *(const uint32_t*)(g_vth + ((size_t)hb * HD_ + d) * N_ + n0 + 2 * i);
                *(uint32_t*)&Vt1[d * P2_STRIDE + 4 * i]     = __byte_perm(v, v, 0x1010);
                *(uint32_t*)&Vt1[d * P2_STRIDE + 4 * i + 2] = __byte_perm(v, v, 0x3232);
                uint32_t u = *(const uint32_t*)(g_vtl + ((size_t)hb * HD_ + d) * N_ + n0 + 2 * i);
                *(uint32_t*)&Vt2[d * P2_STRIDE + 4 * i]     = __byte_perm(u, u, 0x1010);
                *(uint32_t*)&Vt2[d * P2_STRIDE + 4 * i + 2] = __byte_perm(u, u, 0x3232);
            }
        }
        // build Pt: read E rows coalesced, exp, split hi/lo, transpose into SMEM
        {
            float rmx = g_rmax[hb * N_ + n0 + r];
            float rin = 1.0f / g_rsum[hb * N_ + n0 + r];
            const float* Eg = g_E + (size_t)hb * N_ * N_ + (size_t)(n0 + r) * N_ + m0;
#pragma unroll
            for (int k = 0; k < 4; k++) {
                int mc = (c8 + 8 * k) * 4;
                float4 e = *(const float4*)(Eg + mc);
                float pv[4];
                pv[0] = __expf(e.x - rmx) * rin;
                pv[1] = __expf(e.y - rmx) * rin;
                pv[2] = __expf(e.z - rmx) * rin;
                pv[3] = __expf(e.w - rmx) * rin;
#pragma unroll
                for (int i = 0; i < 4; i++) {
                    __nv_bfloat16 ph, pl;
                    split_bf(pv[i], ph, pl);
                    *(uint32_t*)&Pt[(mc + i) * P2_STRIDE + 2 * r] = pk2(ph, pl);
                }
            }
        }
        __syncthreads();

#pragma unroll
        for (int s = 0; s < 8; s++) {
            int k0 = (s & 3) * 16 + 2 * c;
            const __nv_bfloat16* arow = Pt + (16 * w + g) * P2_STRIDE;
            uint32_t a0 = *(const uint32_t*)(arow + k0);
            uint32_t a1 = *(const uint32_t*)(arow + 8 * P2_STRIDE + k0);
            uint32_t a2 = *(const uint32_t*)(arow + k0 + 8);
            uint32_t a3 = *(const uint32_t*)(arow + 8 * P2_STRIDE + k0 + 8);
            const __nv_bfloat16* Vt = (s < 4) ? Vt1 : Vt2;
#pragma unroll
            for (int j = 0; j < 8; j++) {
                const __nv_bfloat16* brow = Vt + (8 * j + g) * P2_STRIDE;
                uint32_t b0 = *(const uint32_t*)(brow + k0);
                uint32_t b1 = *(const uint32_t*)(brow + k0 + 8);
                mma_bf16(acc[j], a0, a1, a2, a3, b0, b1);
            }
        }
    }

    // epilogue: gamma blend + residual
    int h = hb >> 2;
    int b = hb & 3;
    float gam = gamma[h];
    float sc  = 1.0f / (1.0f + gam);
    int m = m0 + 16 * w + g;
#pragma unroll
    for (int j = 0; j < 8; j++) {
        int d = 8 * j + 2 * c;
        float2 y0 = *(const float2*)(g_yp + ((size_t)b * N_ + m) * HD_ + d);
        float2 y1 = *(const float2*)(g_yp + ((size_t)b * N_ + m + 8) * HD_ + d);
        float2 o0 = {(gam * acc[j][0] + y0.x) * sc, (gam * acc[j][1] + y0.y) * sc};
        float2 o1 = {(gam * acc[j][2] + y1.x) * sc, (gam * acc[j][3] + y1.y) * sc};
        *(float2*)(out + ((size_t)hb * N_ + m) * HD_ + d)     = o0;
        *(float2*)(out + ((size_t)hb * N_ + m + 8) * HD_ + d) = o1;
    }
}

// ---------------- launch ----------------
extern "C" void kernel_launch(void* const* d_in, const int* in_sizes, int n_in,
                              void* d_out, int out_size)
{
    const float* x  = (const float*)d_in[0];
    const float* y  = (const float*)d_in[1];
    const float* Wq = (const float*)d_in[2];
    const float* bq = (const float*)d_in[3];
    const float* Wk = (const float*)d_in[4];
    const float* bk = (const float*)d_in[5];
    const float* Wv = (const float*)d_in[6];
    const float* bv = (const float*)d_in[7];
    const float* Wp = (const float*)d_in[8];
    const float* gm = (const float*)d_in[9];
    float* out = (float*)d_out;

    const int smem1 = 2 * 128 * P1_STRIDE * 2;   // 69632 bytes
    cudaFuncSetAttribute(pass1_kernel, cudaFuncAttributeMaxDynamicSharedMemorySize, smem1);

    dim3 blk(256);
    proj_all_kernel<<<dim3(16, 25, 4), blk>>>(Wq, bq, Wk, bk, Wv, bv, Wp, x, y);
    pass1_kernel<<<dim3(16, 32), blk, smem1>>>();
    pass2_kernel<<<dim3(16, 32), blk>>>(gm, out);
}